// round 14
// baseline (speedup 1.0000x reference)
#include <cuda_runtime.h>
#include <cuda_fp16.h>

// ROIAlign via NHWC-fp16 pre-transpose (serial two-kernel):
//   K1: features (2,256,200,304) fp32 NCHW -> g_nhwc (2, 200*304, 256) fp16
//   K2: gather, block = (box, bin-half); lane = 8 contiguous fp16 channels
//       (uint4) -> full 256-channel corner in ONE 512B warp transaction.
//       Bin-split (NOT channel-split): coord math still done once per bin;
//       smem staging 26 KB + reg cap -> 6 blocks/SM (75% occ vs R12's 43%).
// spatial_scale=0.25, sampling_ratio=2, output (1000,256,7,7) fp32.

namespace {

constexpr int C_DIM = 256;
constexpr int H_DIM = 200;
constexpr int W_DIM = 304;
constexpr int S_DIM = H_DIM * W_DIM;        // 60800
constexpr int PH = 7, PW = 7;
constexpr int BINS = PH * PW;               // 49
constexpr float SCALE = 0.25f;
constexpr int S_TILES = S_DIM / 32;         // 1900
constexpr int SM_PITCH = 260;               // floats per staged bin row (>=256)
constexpr int BPB = 25;                     // max bins per block (25 / 24)

__device__ __half g_nhwc[2ull * S_DIM * C_DIM];   // 62.3 MB scratch

__device__ __forceinline__ void axis_interp(float coord, int size,
                                            int& lo, int& hi,
                                            float& frac, bool& valid) {
    valid = (coord >= -1.0f) && (coord <= (float)size);
    float c = fmaxf(coord, 0.0f);
    int low = (int)c;
    if (low >= size - 1) { lo = size - 1; hi = size - 1; frac = 0.0f; }
    else                 { lo = low;      hi = low + 1;  frac = c - (float)low; }
}

// ---------------- K1: NCHW fp32 -> NHWC fp16 transpose ----------------
// Tile: 64 channels x 32 spatial. Reads coalesced along spatial (128B),
// writes coalesced along channel (uint = 2 halves per lane, 128B rows).
__global__ __launch_bounds__(256)
void transpose_kernel(const float* __restrict__ feat) {
    __shared__ __half tile[32][66];     // [spatial][channel], +2 pad

    int bid = blockIdx.x;
    int ct  = bid & 3;                  // 4 channel tiles of 64
    int st  = (bid >> 2) % S_TILES;
    int n   = bid / (4 * S_TILES);
    int c0  = ct * 64;
    int s0  = st * 32;

    int lane = threadIdx.x & 31;
    int grp  = threadIdx.x >> 5;        // 0..7

    const float* src = feat + ((size_t)(n * C_DIM + c0)) * S_DIM + s0;
#pragma unroll
    for (int it = 0; it < 8; it++) {
        int c = it * 8 + grp;
        tile[lane][c] = __float2half(src[(size_t)c * S_DIM + lane]);
    }
    __syncthreads();

    const unsigned* tw = (const unsigned*)&tile[0][0];   // 33 words per row
    unsigned* dst = (unsigned*)(g_nhwc + ((size_t)n * S_DIM + s0) * C_DIM + c0);
#pragma unroll
    for (int it = 0; it < 4; it++) {
        int s = it * 8 + grp;
        dst[(size_t)s * (C_DIM / 2) + lane] = tw[s * 33 + lane];
    }
}

// ---------------- K2: gather ----------------
// Block = (box, bin-half h): bins [25h, min(25h+25, 49)). 8 warps; warp w
// does local bins sl = w, w+8, ... Lane = channels lane*8..+7 via uint4.
__global__ __launch_bounds__(256, 6)
void gather_kernel(const float* __restrict__ boxes,
                   float* __restrict__ out, int R) {
    __shared__ float sm[BPB * SM_PITCH];    // 26 KB

    int bid  = blockIdx.x;
    int r    = bid >> 1;                    // box
    int h    = bid & 1;                     // bin half
    int s0   = h * BPB;                     // first global bin
    int nbin = h ? (BINS - BPB) : BPB;      // 24 : 25

    int tid  = threadIdx.x;
    int lane = tid & 31;
    int w    = tid >> 5;

    const float* bx = boxes + (size_t)r * 5;
    int   nb = (int)__ldg(bx + 0);
    float x1 = __ldg(bx + 1) * SCALE;
    float y1 = __ldg(bx + 2) * SCALE;
    float x2 = __ldg(bx + 3) * SCALE;
    float y2 = __ldg(bx + 4) * SCALE;
    float bin_w = fmaxf(x2 - x1, 1.0f) * (1.0f / PW);
    float bin_h = fmaxf(y2 - y1, 1.0f) * (1.0f / PH);

    const __half* base = g_nhwc + (size_t)nb * S_DIM * C_DIM + (lane << 3);

    for (int sl = w; sl < nbin; sl += 8) {
        int s  = s0 + sl;
        int ph = s / PW, pw = s % PW;

        // 4 candidate rows (2 samples x lo/hi) and 4 candidate cols with
        // axis validity folded into weights; 0.25 mean folded into wy.
        int   ro[4], xo[4];
        float wy[4], wx[4];
#pragma unroll
        for (int i = 0; i < 2; i++) {
            float yc = y1 + ((float)ph + ((float)i + 0.5f) * 0.5f) * bin_h;
            float xc = x1 + ((float)pw + ((float)i + 0.5f) * 0.5f) * bin_w;
            int yl, yh, xl, xh; float fy, fx; bool vy, vx;
            axis_interp(yc, H_DIM, yl, yh, fy, vy);
            axis_interp(xc, W_DIM, xl, xh, fx, vx);
            ro[2 * i]     = (yl * W_DIM) * C_DIM;
            ro[2 * i + 1] = (yh * W_DIM) * C_DIM;
            wy[2 * i]     = vy ? (1.0f - fy) * 0.25f : 0.0f;
            wy[2 * i + 1] = vy ? fy * 0.25f          : 0.0f;
            xo[2 * i]     = xl * C_DIM;
            xo[2 * i + 1] = xh * C_DIM;
            wx[2 * i]     = vx ? (1.0f - fx) : 0.0f;
            wx[2 * i + 1] = vx ? fx          : 0.0f;
        }

        float a0 = 0.f, a1 = 0.f, a2 = 0.f, a3 = 0.f;
        float a4 = 0.f, a5 = 0.f, a6 = 0.f, a7 = 0.f;

        // One sample-row per batch: 4 independent uint4 loads issued
        // back-to-back; consumption overlaps the next row's loads.
#pragma unroll
        for (int a = 0; a < 4; a++) {
            const __half* rp = base + ro[a];
            uint4 v[4];
#pragma unroll
            for (int b2 = 0; b2 < 4; b2++)
                v[b2] = __ldg((const uint4*)(rp + xo[b2]));
#pragma unroll
            for (int b2 = 0; b2 < 4; b2++) {
                float wgt = wy[a] * wx[b2];
                float2 f0 = __half22float2(*(const __half2*)&v[b2].x);
                float2 f1 = __half22float2(*(const __half2*)&v[b2].y);
                float2 f2 = __half22float2(*(const __half2*)&v[b2].z);
                float2 f3 = __half22float2(*(const __half2*)&v[b2].w);
                a0 += wgt * f0.x;  a1 += wgt * f0.y;
                a2 += wgt * f1.x;  a3 += wgt * f1.y;
                a4 += wgt * f2.x;  a5 += wgt * f2.y;
                a6 += wgt * f3.x;  a7 += wgt * f3.y;
            }
        }

        // Stage channels lane*8..+7 (max float offset 255 < 260) as 4x
        // float2 (pitch*4 = 1040 B, lane offset 32 B -> 8B aligned).
        float2* row = (float2*)(sm + sl * SM_PITCH) + (lane << 2);
        row[0] = make_float2(a0, a1);
        row[1] = make_float2(a2, a3);
        row[2] = make_float2(a4, a5);
        row[3] = make_float2(a6, a7);
    }
    __syncthreads();

    // Epilogue: this block's (256 ch x nbin bins) slice of the output.
    // Ordering keeps STG coalesced (25-float contiguous runs per channel).
    float* o = out + (size_t)r * (C_DIM * BINS) + s0;
    int total = C_DIM * nbin;
    for (int q = tid; q < total; q += 256) {
        int c  = q / nbin;
        int sb = q - c * nbin;
        o[c * BINS + sb] = sm[sb * SM_PITCH + c];
    }
}

} // namespace

extern "C" void kernel_launch(void* const* d_in, const int* in_sizes, int n_in,
                              void* d_out, int out_size) {
    const float* features = (const float*)d_in[0];
    const float* boxes    = (const float*)d_in[1];
    float*       out      = (float*)d_out;

    int R = in_sizes[1] / 5;                          // 1000 boxes

    int tblocks = 2 * 4 * S_TILES;                    // 15200
    transpose_kernel<<<tblocks, 256>>>(features);
    gather_kernel<<<2 * R, 256>>>(boxes, out, R);
}

// round 15
// speedup vs baseline: 1.1025x; 1.1025x over previous
#include <cuda_runtime.h>
#include <cuda_fp16.h>

// ROIAlign via NHWC-fp16 pre-transpose (serial two-kernel, R12 structure):
//   K1: features (2,256,200,304) fp32 NCHW -> g_nhwc (2, 200*304, 256) fp16
//   K2: gather, block = one box (grid 1000); lane = 8 contiguous fp16
//       channels (uint4) -> full 256-channel corner in ONE 512B transaction.
//       Inner math in half2 (__hfma2) with per-sample-row fp32 promotion:
//       ~2x fewer math instructions on the issue-bound loop. 51 KB dynamic
//       smem staging (pitch 260 >= 256).
// spatial_scale=0.25, sampling_ratio=2, output (1000,256,7,7) fp32.

namespace {

constexpr int C_DIM = 256;
constexpr int H_DIM = 200;
constexpr int W_DIM = 304;
constexpr int S_DIM = H_DIM * W_DIM;        // 60800
constexpr int PH = 7, PW = 7;
constexpr int BINS = PH * PW;               // 49
constexpr float SCALE = 0.25f;
constexpr int S_TILES = S_DIM / 32;         // 1900
constexpr int SM_PITCH = 260;               // floats per bin row (>=256 + pad)
constexpr int SMEM_BYTES = BINS * SM_PITCH * 4;   // 50960 B (dynamic)

__device__ __half g_nhwc[2ull * S_DIM * C_DIM];   // 62.3 MB scratch

__device__ __forceinline__ void axis_interp(float coord, int size,
                                            int& lo, int& hi,
                                            float& frac, bool& valid) {
    valid = (coord >= -1.0f) && (coord <= (float)size);
    float c = fmaxf(coord, 0.0f);
    int low = (int)c;
    if (low >= size - 1) { lo = size - 1; hi = size - 1; frac = 0.0f; }
    else                 { lo = low;      hi = low + 1;  frac = c - (float)low; }
}

// ---------------- K1: NCHW fp32 -> NHWC fp16 transpose ----------------
// Tile: 64 channels x 32 spatial. Reads coalesced along spatial (128B),
// writes coalesced along channel (uint = 2 halves per lane, 128B rows).
__global__ __launch_bounds__(256)
void transpose_kernel(const float* __restrict__ feat) {
    __shared__ __half tile[32][66];     // [spatial][channel], +2 pad

    int bid = blockIdx.x;
    int ct  = bid & 3;                  // 4 channel tiles of 64
    int st  = (bid >> 2) % S_TILES;
    int n   = bid / (4 * S_TILES);
    int c0  = ct * 64;
    int s0  = st * 32;

    int lane = threadIdx.x & 31;
    int grp  = threadIdx.x >> 5;        // 0..7

    const float* src = feat + ((size_t)(n * C_DIM + c0)) * S_DIM + s0;
#pragma unroll
    for (int it = 0; it < 8; it++) {
        int c = it * 8 + grp;
        tile[lane][c] = __float2half(src[(size_t)c * S_DIM + lane]);
    }
    __syncthreads();

    const unsigned* tw = (const unsigned*)&tile[0][0];   // 33 words per row
    unsigned* dst = (unsigned*)(g_nhwc + ((size_t)n * S_DIM + s0) * C_DIM + c0);
#pragma unroll
    for (int it = 0; it < 4; it++) {
        int s = it * 8 + grp;
        dst[(size_t)s * (C_DIM / 2) + lane] = tw[s * 33 + lane];
    }
}

// ---------------- K2: gather ----------------
// Block = one box; 8 warps; warp w does bins s = w, w+8, ...
// Lane supplies channels lane*8 .. lane*8+7 via one uint4 (8 fp16).
__global__ __launch_bounds__(256, 4)
void gather_kernel(const float* __restrict__ boxes,
                   float* __restrict__ out) {
    extern __shared__ float sm[];           // BINS * SM_PITCH floats (51 KB)

    int r    = blockIdx.x;
    int tid  = threadIdx.x;
    int lane = tid & 31;
    int w    = tid >> 5;

    const float* bx = boxes + (size_t)r * 5;
    int   nb = (int)__ldg(bx + 0);
    float x1 = __ldg(bx + 1) * SCALE;
    float y1 = __ldg(bx + 2) * SCALE;
    float x2 = __ldg(bx + 3) * SCALE;
    float y2 = __ldg(bx + 4) * SCALE;
    float bin_w = fmaxf(x2 - x1, 1.0f) * (1.0f / PW);
    float bin_h = fmaxf(y2 - y1, 1.0f) * (1.0f / PH);

    const __half* base = g_nhwc + (size_t)nb * S_DIM * C_DIM + (lane << 3);

    for (int s = w; s < BINS; s += 8) {
        int ph = s / PW, pw = s % PW;

        // 4 candidate rows (2 samples x lo/hi) and 4 candidate cols with
        // axis validity folded into the weights; 0.25 sample-mean folded
        // into wy. All lane-uniform.
        int   ro[4], xo[4];
        float wy[4], wx[4];
#pragma unroll
        for (int i = 0; i < 2; i++) {
            float yc = y1 + ((float)ph + ((float)i + 0.5f) * 0.5f) * bin_h;
            float xc = x1 + ((float)pw + ((float)i + 0.5f) * 0.5f) * bin_w;
            int yl, yh, xl, xh; float fy, fx; bool vy, vx;
            axis_interp(yc, H_DIM, yl, yh, fy, vy);
            axis_interp(xc, W_DIM, xl, xh, fx, vx);
            ro[2 * i]     = (yl * W_DIM) * C_DIM;
            ro[2 * i + 1] = (yh * W_DIM) * C_DIM;
            wy[2 * i]     = vy ? (1.0f - fy) * 0.25f : 0.0f;
            wy[2 * i + 1] = vy ? fy * 0.25f          : 0.0f;
            xo[2 * i]     = xl * C_DIM;
            xo[2 * i + 1] = xh * C_DIM;
            wx[2 * i]     = vx ? (1.0f - fx) : 0.0f;
            wx[2 * i + 1] = vx ? fx          : 0.0f;
        }

        float a0 = 0.f, a1 = 0.f, a2 = 0.f, a3 = 0.f;
        float a4 = 0.f, a5 = 0.f, a6 = 0.f, a7 = 0.f;

        // One sample-row per batch: 4 independent uint4 loads issued
        // back-to-back. Within-row accumulation in half2 (4-FMA chains on
        // partials <= 0.25 -> bounded rounding), promoted to fp32 per row.
#pragma unroll
        for (int a = 0; a < 4; a++) {
            const __half* rp = base + ro[a];
            uint4 v[4];
#pragma unroll
            for (int b2 = 0; b2 < 4; b2++)
                v[b2] = __ldg((const uint4*)(rp + xo[b2]));

            __half2 r0 = __float2half2_rn(0.f);
            __half2 r1 = r0, r2 = r0, r3 = r0;
#pragma unroll
            for (int b2 = 0; b2 < 4; b2++) {
                __half2 w2 = __float2half2_rn(wy[a] * wx[b2]);
                r0 = __hfma2(w2, *(const __half2*)&v[b2].x, r0);
                r1 = __hfma2(w2, *(const __half2*)&v[b2].y, r1);
                r2 = __hfma2(w2, *(const __half2*)&v[b2].z, r2);
                r3 = __hfma2(w2, *(const __half2*)&v[b2].w, r3);
            }
            float2 f0 = __half22float2(r0);
            float2 f1 = __half22float2(r1);
            float2 f2 = __half22float2(r2);
            float2 f3 = __half22float2(r3);
            a0 += f0.x;  a1 += f0.y;
            a2 += f1.x;  a3 += f1.y;
            a4 += f2.x;  a5 += f2.y;
            a6 += f3.x;  a7 += f3.y;
        }

        // Stage channels lane*8 .. lane*8+7 (max float offset 255 < 260)
        // as 4x float2 (pitch*4 = 1040 B, lane offset 32 B -> 8B aligned).
        float2* row = (float2*)(sm + s * SM_PITCH) + (lane << 2);
        row[0] = make_float2(a0, a1);
        row[1] = make_float2(a2, a3);
        row[2] = make_float2(a4, a5);
        row[3] = make_float2(a6, a7);
    }
    __syncthreads();

    // Coalesced epilogue: box's (256 ch x 49 bins) block is contiguous in
    // the (R, C, 7, 7) output.
    float* o = out + (size_t)r * (C_DIM * BINS);
    for (int q = tid; q < C_DIM * BINS; q += 256) {
        int c  = q / BINS;
        int sb = q - c * BINS;
        o[q] = sm[sb * SM_PITCH + c];
    }
}

} // namespace

extern "C" void kernel_launch(void* const* d_in, const int* in_sizes, int n_in,
                              void* d_out, int out_size) {
    const float* features = (const float*)d_in[0];
    const float* boxes    = (const float*)d_in[1];
    float*       out      = (float*)d_out;

    int R = in_sizes[1] / 5;                          // 1000 boxes

    // Allow >48KB dynamic smem for the gather (idempotent, capture-safe).
    cudaFuncSetAttribute(gather_kernel,
                         cudaFuncAttributeMaxDynamicSharedMemorySize,
                         SMEM_BYTES);

    int tblocks = 2 * 4 * S_TILES;                    // 15200
    transpose_kernel<<<tblocks, 256>>>(features);
    gather_kernel<<<R, 256, SMEM_BYTES>>>(boxes, out);
}

// round 16
// speedup vs baseline: 1.1790x; 1.0694x over previous
#include <cuda_runtime.h>
#include <cuda_fp16.h>

// ROIAlign via NHWC-fp16 pre-transpose (serial two-kernel):
//   K1: features (2,256,200,304) fp32 NCHW -> g_nhwc (2, 200*304, 256) fp16
//   K2: gather, block = one box (grid 1000); lane = 8 contiguous fp16
//       channels (uint4) -> full 256-channel corner in ONE 512B transaction.
//       half2 inner math with per-sample-row fp32 promotion. Staging in
//       fp16 (25.9 KB static smem) + __launch_bounds__(256,5): both the
//       smem and register occupancy caps lifted together -> ~62% occ while
//       keeping the 4x uint4 load batches (MLP) intact.
// spatial_scale=0.25, sampling_ratio=2, output (1000,256,7,7) fp32.

namespace {

constexpr int C_DIM = 256;
constexpr int H_DIM = 200;
constexpr int W_DIM = 304;
constexpr int S_DIM = H_DIM * W_DIM;        // 60800
constexpr int PH = 7, PW = 7;
constexpr int BINS = PH * PW;               // 49
constexpr float SCALE = 0.25f;
constexpr int S_TILES = S_DIM / 32;         // 1900
constexpr int SM_PITCH_H = 264;             // halves per staged bin row
                                            // (>=256, row stride 528B = 33*16B
                                            //  -> uint4 STS stays 16B-aligned)

__device__ __half g_nhwc[2ull * S_DIM * C_DIM];   // 62.3 MB scratch

__device__ __forceinline__ void axis_interp(float coord, int size,
                                            int& lo, int& hi,
                                            float& frac, bool& valid) {
    valid = (coord >= -1.0f) && (coord <= (float)size);
    float c = fmaxf(coord, 0.0f);
    int low = (int)c;
    if (low >= size - 1) { lo = size - 1; hi = size - 1; frac = 0.0f; }
    else                 { lo = low;      hi = low + 1;  frac = c - (float)low; }
}

// ---------------- K1: NCHW fp32 -> NHWC fp16 transpose ----------------
// Tile: 64 channels x 32 spatial. Reads coalesced along spatial (128B),
// writes coalesced along channel (uint = 2 halves per lane, 128B rows).
__global__ __launch_bounds__(256)
void transpose_kernel(const float* __restrict__ feat) {
    __shared__ __half tile[32][66];     // [spatial][channel], +2 pad

    int bid = blockIdx.x;
    int ct  = bid & 3;                  // 4 channel tiles of 64
    int st  = (bid >> 2) % S_TILES;
    int n   = bid / (4 * S_TILES);
    int c0  = ct * 64;
    int s0  = st * 32;

    int lane = threadIdx.x & 31;
    int grp  = threadIdx.x >> 5;        // 0..7

    const float* src = feat + ((size_t)(n * C_DIM + c0)) * S_DIM + s0;
#pragma unroll
    for (int it = 0; it < 8; it++) {
        int c = it * 8 + grp;
        tile[lane][c] = __float2half(src[(size_t)c * S_DIM + lane]);
    }
    __syncthreads();

    const unsigned* tw = (const unsigned*)&tile[0][0];   // 33 words per row
    unsigned* dst = (unsigned*)(g_nhwc + ((size_t)n * S_DIM + s0) * C_DIM + c0);
#pragma unroll
    for (int it = 0; it < 4; it++) {
        int s = it * 8 + grp;
        dst[(size_t)s * (C_DIM / 2) + lane] = tw[s * 33 + lane];
    }
}

// ---------------- K2: gather ----------------
// Block = one box; 8 warps; warp w does bins s = w, w+8, ...
// Lane supplies channels lane*8 .. lane*8+7 via one uint4 (8 fp16).
__global__ __launch_bounds__(256, 5)
void gather_kernel(const float* __restrict__ boxes,
                   float* __restrict__ out) {
    __shared__ __half smh[BINS * SM_PITCH_H];   // 25.9 KB

    int r    = blockIdx.x;
    int tid  = threadIdx.x;
    int lane = tid & 31;
    int w    = tid >> 5;

    const float* bx = boxes + (size_t)r * 5;
    int   nb = (int)__ldg(bx + 0);
    float x1 = __ldg(bx + 1) * SCALE;
    float y1 = __ldg(bx + 2) * SCALE;
    float x2 = __ldg(bx + 3) * SCALE;
    float y2 = __ldg(bx + 4) * SCALE;
    float bin_w = fmaxf(x2 - x1, 1.0f) * (1.0f / PW);
    float bin_h = fmaxf(y2 - y1, 1.0f) * (1.0f / PH);

    const __half* base = g_nhwc + (size_t)nb * S_DIM * C_DIM + (lane << 3);

    for (int s = w; s < BINS; s += 8) {
        int ph = s / PW, pw = s % PW;

        // 4 candidate rows (2 samples x lo/hi) and 4 candidate cols with
        // axis validity folded into the weights; 0.25 sample-mean folded
        // into wy. All lane-uniform.
        int   ro[4], xo[4];
        float wy[4], wx[4];
#pragma unroll
        for (int i = 0; i < 2; i++) {
            float yc = y1 + ((float)ph + ((float)i + 0.5f) * 0.5f) * bin_h;
            float xc = x1 + ((float)pw + ((float)i + 0.5f) * 0.5f) * bin_w;
            int yl, yh, xl, xh; float fy, fx; bool vy, vx;
            axis_interp(yc, H_DIM, yl, yh, fy, vy);
            axis_interp(xc, W_DIM, xl, xh, fx, vx);
            ro[2 * i]     = (yl * W_DIM) * C_DIM;
            ro[2 * i + 1] = (yh * W_DIM) * C_DIM;
            wy[2 * i]     = vy ? (1.0f - fy) * 0.25f : 0.0f;
            wy[2 * i + 1] = vy ? fy * 0.25f          : 0.0f;
            xo[2 * i]     = xl * C_DIM;
            xo[2 * i + 1] = xh * C_DIM;
            wx[2 * i]     = vx ? (1.0f - fx) : 0.0f;
            wx[2 * i + 1] = vx ? fx          : 0.0f;
        }

        float a0 = 0.f, a1 = 0.f, a2 = 0.f, a3 = 0.f;
        float a4 = 0.f, a5 = 0.f, a6 = 0.f, a7 = 0.f;

        // One sample-row per batch: 4 independent uint4 loads issued
        // back-to-back. Within-row accumulation in half2 (4-FMA chains on
        // partials <= 0.25 -> bounded rounding), promoted to fp32 per row.
#pragma unroll
        for (int a = 0; a < 4; a++) {
            const __half* rp = base + ro[a];
            uint4 v[4];
#pragma unroll
            for (int b2 = 0; b2 < 4; b2++)
                v[b2] = __ldg((const uint4*)(rp + xo[b2]));

            __half2 r0 = __float2half2_rn(0.f);
            __half2 r1 = r0, r2 = r0, r3 = r0;
#pragma unroll
            for (int b2 = 0; b2 < 4; b2++) {
                __half2 w2 = __float2half2_rn(wy[a] * wx[b2]);
                r0 = __hfma2(w2, *(const __half2*)&v[b2].x, r0);
                r1 = __hfma2(w2, *(const __half2*)&v[b2].y, r1);
                r2 = __hfma2(w2, *(const __half2*)&v[b2].z, r2);
                r3 = __hfma2(w2, *(const __half2*)&v[b2].w, r3);
            }
            float2 f0 = __half22float2(r0);
            float2 f1 = __half22float2(r1);
            float2 f2 = __half22float2(r2);
            float2 f3 = __half22float2(r3);
            a0 += f0.x;  a1 += f0.y;
            a2 += f1.x;  a3 += f1.y;
            a4 += f2.x;  a5 += f2.y;
            a6 += f3.x;  a7 += f3.y;
        }

        // Stage channels lane*8..+7 as fp16: one 16B uint4 STS per lane
        // (row stride 528B and lane offset 16B keep it aligned,
        //  32 lanes span 512B contiguous -> conflict-free).
        uint4 pk;
        __half2 h0 = __floats2half2_rn(a0, a1);
        __half2 h1 = __floats2half2_rn(a2, a3);
        __half2 h2 = __floats2half2_rn(a4, a5);
        __half2 h3 = __floats2half2_rn(a6, a7);
        pk.x = *(const unsigned*)&h0;
        pk.y = *(const unsigned*)&h1;
        pk.z = *(const unsigned*)&h2;
        pk.w = *(const unsigned*)&h3;
        ((uint4*)(smh + s * SM_PITCH_H))[lane] = pk;
    }
    __syncthreads();

    // Coalesced epilogue: box's (256 ch x 49 bins) block is contiguous in
    // the (R, C, 7, 7) output.
    float* o = out + (size_t)r * (C_DIM * BINS);
    for (int q = tid; q < C_DIM * BINS; q += 256) {
        int c  = q / BINS;
        int sb = q - c * BINS;
        o[q] = __half2float(smh[sb * SM_PITCH_H + c]);
    }
}

} // namespace

extern "C" void kernel_launch(void* const* d_in, const int* in_sizes, int n_in,
                              void* d_out, int out_size) {
    const float* features = (const float*)d_in[0];
    const float* boxes    = (const float*)d_in[1];
    float*       out      = (float*)d_out;

    int R = in_sizes[1] / 5;                          // 1000 boxes

    int tblocks = 2 * 4 * S_TILES;                    // 15200
    transpose_kernel<<<tblocks, 256>>>(features);
    gather_kernel<<<R, 256>>>(boxes, out);
}